// round 10
// baseline (speedup 1.0000x reference)
#include <cuda_runtime.h>
#include <math.h>

#define NN 50000
#define EE 800000
#define FIN 32
#define FOUT 64
#define CIN 160    // 5 blocks of 32
#define COUT 128   // 2 gates x 64

// ---------------- scratch (device globals; no allocation) ----------------
__device__ float g_degin[NN], g_degout[NN];
__device__ int   g_cntin[NN], g_cntout[NN], g_fill[NN];
__device__ int   g_instart[NN + 1], g_outstart[NN + 1];
__device__ int   g_bucket[EE];
__device__ int   g_csc_src[EE];
__device__ float g_csc_coef[EE];
__device__ float g_ci[EE];
__device__ int   g_T;   // # edges whose int32 key (dst*N+src) overflows negative
__device__ __align__(16) float g_Y1o[NN * FIN];
__device__ __align__(16) float g_Y1i[NN * FIN];
__device__ __align__(16) float g_U2o[NN * FIN];
__device__ __align__(16) float g_U2i[NN * FIN];
__device__ __align__(16) float g_L[NN * COUT];
__device__ __align__(16) float g_Wc[CIN * COUT];
__device__ float g_bc[COUT];

// ---------------- preprocessing ----------------
__global__ void k_zero() {
    int i = blockIdx.x * blockDim.x + threadIdx.x;
    if (i < NN) {
        g_degin[i] = 0.f; g_degout[i] = 0.f;
        g_cntin[i] = 0;   g_cntout[i] = 0;  g_fill[i] = 0;
    }
    if (i == 0) g_T = 0;
}

__global__ void k_hist(const int* __restrict__ src, const int* __restrict__ dst,
                       const float* __restrict__ w) {
    int j = blockIdx.x * blockDim.x + threadIdx.x;
    if (j < EE) {
        int s = src[j], d = dst[j];
        float ww = w[j];
        atomicAdd(&g_cntout[s], 1);
        atomicAdd(&g_cntin[d], 1);
        atomicAdd(&g_degout[s], ww);
        atomicAdd(&g_degin[d], ww);
        // Reference computes argsort keys dst*N+src in int32 (JAX x64 disabled):
        // keys >= 2^31 wrap negative and sort FIRST. Count them (warp-aggregated).
        bool hi = ((long long)d * (long long)NN + (long long)s) >= 2147483648LL;
        unsigned m = __ballot_sync(__activemask(), hi);
        if ((threadIdx.x & 31) == 0 && m) atomicAdd(&g_T, __popc(m));
    }
}

// single-block chunked exclusive scan (N=50000, trivial cost)
__device__ void scan_one(const int* cnt, int* out) {
    __shared__ int warpsum[32];
    __shared__ int s_carry;
    if (threadIdx.x == 0) s_carry = 0;
    __syncthreads();
    int lane = threadIdx.x & 31, wid = threadIdx.x >> 5;
    for (int base = 0; base < NN; base += blockDim.x) {
        int i = base + (int)threadIdx.x;
        int v = (i < NN) ? cnt[i] : 0;
        int x = v;
#pragma unroll
        for (int o = 1; o < 32; o <<= 1) {
            int t = __shfl_up_sync(0xffffffff, x, o);
            if (lane >= o) x += t;
        }
        if (lane == 31) warpsum[wid] = x;
        __syncthreads();
        if (wid == 0) {
            int nw = blockDim.x >> 5;
            int ws = (lane < nw) ? warpsum[lane] : 0;
#pragma unroll
            for (int o = 1; o < 32; o <<= 1) {
                int t = __shfl_up_sync(0xffffffff, ws, o);
                if (lane >= o) ws += t;
            }
            warpsum[lane] = ws;
        }
        __syncthreads();
        int incl = x + (wid > 0 ? warpsum[wid - 1] : 0);
        int carry = s_carry;
        if (i < NN) out[i] = carry + incl - v;
        __syncthreads();
        if (threadIdx.x == blockDim.x - 1) s_carry = carry + incl;
        __syncthreads();
    }
    if (threadIdx.x == 0) out[NN] = s_carry;
    __syncthreads();
}

__global__ void k_scan() {
    scan_one(g_cntin, g_instart);
    scan_one(g_cntout, g_outstart);
}

__global__ void k_bucket(const int* __restrict__ dst) {
    int j = blockIdx.x * blockDim.x + threadIdx.x;
    if (j < EE) {
        int d = dst[j];
        int t = atomicAdd(&g_fill[d], 1);
        g_bucket[g_instart[d] + t] = j;
    }
}

// Per-dst insertion sort (stable by src == by j), then fill CSC arrays.
// Position t in the bucket array is the pure (dst,src) rank. The reference's
// actual order (int32-overflowed keys) is a ROTATION: edges with key64 >= 2^31
// (T of them) come first. So edge at pure rank t sits at reference position
// tref = (t + T) mod E, and its reverse coefficient is 1/deg_in[src[tref]]
// (norm_in indexed by POSITION in the reference's rev arrays).
__global__ void k_sortfill(const int* __restrict__ src) {
    int i = blockIdx.x * blockDim.x + threadIdx.x;
    if (i >= NN) return;
    int T = g_T;
    int b = g_instart[i], e = g_instart[i + 1];
    for (int p = b + 1; p < e; p++) {
        int v = g_bucket[p];
        int q = p - 1;
        while (q >= b && g_bucket[q] > v) { g_bucket[q + 1] = g_bucket[q]; q--; }
        g_bucket[q + 1] = v;
    }
    for (int t = b; t < e; t++) {
        int j = g_bucket[t];
        int s = src[j];
        g_csc_src[t] = s;
        g_csc_coef[t] = 1.0f / g_degout[s];       // norm_out for forward edge j
        int tref = t + T; if (tref >= EE) tref -= EE;
        g_ci[j] = 1.0f / g_degin[src[tref]];      // norm_in indexed by ref POSITION
    }
}

// ---------------- propagation (pure gather, no atomics) ----------------
// PHASE 0: Y1o = P_o X, Y1i = P_i X;  PHASE 1: U2o = P_o Y1o, U2i = P_i Y1i
template <int PHASE>
__global__ void k_prop(const float* __restrict__ X, const int* __restrict__ dst) {
    int warp = (blockIdx.x * blockDim.x + threadIdx.x) >> 5;
    int lane = threadIdx.x & 31;
    if (warp >= NN) return;
    const float* inF = PHASE ? g_Y1o : X;
    const float* inR = PHASE ? g_Y1i : X;
    float* outF = PHASE ? g_U2o : g_Y1o;
    float* outR = PHASE ? g_U2i : g_Y1i;
    int i = warp;

    float accF = 0.f;
    int b = g_instart[i], e = g_instart[i + 1];
    for (int t = b; t < e; t++)
        accF += g_csc_coef[t] * inF[g_csc_src[t] * FIN + lane];

    float accR = 0.f;
    int b2 = g_outstart[i], e2 = g_outstart[i + 1];
    for (int j = b2; j < e2; j++)
        accR += g_ci[j] * inR[dst[j] * FIN + lane];

    outF[i * FIN + lane] = accF;
    outR[i * FIN + lane] = accR;
}

// ---------------- combined weight build (top-32 rows only, H==0) ----------------
__global__ void k_buildW(const float* __restrict__ Wz, const float* __restrict__ bz,
                         const float* __restrict__ Wh, const float* __restrict__ bh) {
    int idx = blockIdx.x * blockDim.x + threadIdx.x;
    if (idx >= CIN * COUT) return;
    int R = idx / COUT, C = idx % COUT;
    int gate = C / FOUT, c = C % FOUT;
    const float* W = gate ? Wh : Wz;  // W[d][k][r][c], shape (2,3,96,64)
    int blk = R / 32, r = R % 32;
#define WV(d, k) W[(((d) * 3 + (k)) * 96 + r) * 64 + c]
    float v;
    if (blk == 0)      v = WV(0, 0) + WV(1, 0) - WV(0, 2) - WV(1, 2);
    else if (blk == 1) v = WV(0, 1);
    else if (blk == 2) v = WV(1, 1);
    else if (blk == 3) v = 2.f * WV(0, 2);
    else               v = 2.f * WV(1, 2);
#undef WV
    g_Wc[R * COUT + C] = v;
    if (R == 0) g_bc[C] = gate ? bh[c] : bz[c];
}

// ---------------- GEMM: L = [X|Y1o|Y1i|U2o|U2i] @ Wc + bc ----------------
// Full 160x128 W in smem (80KB) + 128x33 F tile (16.9KB). 512 threads,
// each computes 4 nodes x 8 cols.
__global__ __launch_bounds__(512, 1) void k_gemm(const float* __restrict__ X) {
    extern __shared__ float sm[];
    float* Ws = sm;                  // [160][128]
    float* Fs = sm + CIN * COUT;     // [128][33] padded

    int tid = threadIdx.x;
    for (int p = tid; p < CIN * COUT / 4; p += 512)
        ((float4*)Ws)[p] = ((const float4*)g_Wc)[p];

    int nodeBase = blockIdx.x * 128;
    int tx = tid & 15;   // 16 col groups x 8 cols
    int ty = tid >> 4;   // 32 node groups x 4 nodes
    float acc[4][8];
#pragma unroll
    for (int a = 0; a < 4; a++)
#pragma unroll
        for (int q = 0; q < 8; q++) acc[a][q] = 0.f;

    for (int kc = 0; kc < 5; kc++) {
        __syncthreads();
        const float* A;
        if (kc == 0) A = X;
        else if (kc == 1) A = g_Y1o;
        else if (kc == 2) A = g_Y1i;
        else if (kc == 3) A = g_U2o;
        else A = g_U2i;
        // stage 128 nodes x 32 feats
        for (int p = tid; p < 128 * 8; p += 512) {
            int nn = p >> 3;
            int kk4 = p & 7;
            int node = nodeBase + nn;
            float4 v = make_float4(0.f, 0.f, 0.f, 0.f);
            if (node < NN) v = ((const float4*)(A + (size_t)node * FIN))[kk4];
            float* dp = &Fs[nn * 33 + kk4 * 4];
            dp[0] = v.x; dp[1] = v.y; dp[2] = v.z; dp[3] = v.w;
        }
        __syncthreads();
#pragma unroll 8
        for (int kk = 0; kk < 32; kk++) {
            int k = kc * 32 + kk;
            float fr[4];
#pragma unroll
            for (int a = 0; a < 4; a++) fr[a] = Fs[(ty * 4 + a) * 33 + kk];
            float4 w0 = *((float4*)&Ws[k * COUT + tx * 8]);
            float4 w1 = *((float4*)&Ws[k * COUT + tx * 8 + 4]);
            float wr[8] = {w0.x, w0.y, w0.z, w0.w, w1.x, w1.y, w1.z, w1.w};
#pragma unroll
            for (int a = 0; a < 4; a++)
#pragma unroll
                for (int q = 0; q < 8; q++) acc[a][q] += fr[a] * wr[q];
        }
    }
#pragma unroll
    for (int a = 0; a < 4; a++) {
        int node = nodeBase + ty * 4 + a;
        if (node < NN) {
#pragma unroll
            for (int q = 0; q < 8; q++)
                g_L[(size_t)node * COUT + tx * 8 + q] = acc[a][q] + g_bc[tx * 8 + q];
        }
    }
}

// ---------------- epilogue: out = (1 - sigmoid(z)) * tanh(h) ----------------
__global__ void k_final(float* __restrict__ out) {
    int idx = blockIdx.x * blockDim.x + threadIdx.x;
    if (idx >= NN * FOUT) return;
    int i = idx >> 6, c = idx & 63;
    float z = g_L[(size_t)i * COUT + c];
    float h = g_L[(size_t)i * COUT + 64 + c];
    float omz = 1.f / (1.f + expf(z));  // 1 - sigmoid(z) = sigmoid(-z)
    out[idx] = omz * tanhf(h);
}

// ---------------- launch ----------------
extern "C" void kernel_launch(void* const* d_in, const int* in_sizes, int n_in,
                              void* d_out, int out_size) {
    const float* X  = (const float*)d_in[0];
    const int*   ei = (const int*)d_in[1];
    const float* ew = (const float*)d_in[2];
    const float* Wz = (const float*)d_in[3];
    const float* bz = (const float*)d_in[4];
    // d_in[5]=Wr, d_in[6]=br are mathematically dead (H==0)
    const float* Wh = (const float*)d_in[7];
    const float* bh = (const float*)d_in[8];
    const int* src = ei;
    const int* dst = ei + EE;
    float* out = (float*)d_out;

    (void)in_sizes; (void)n_in; (void)out_size;

    cudaFuncSetAttribute(k_gemm, cudaFuncAttributeMaxDynamicSharedMemorySize,
                         (CIN * COUT + 128 * 33) * 4);

    k_zero<<<(NN + 255) / 256, 256>>>();
    k_hist<<<(EE + 255) / 256, 256>>>(src, dst, ew);
    k_scan<<<1, 1024>>>();
    k_bucket<<<(EE + 255) / 256, 256>>>(dst);
    k_sortfill<<<(NN + 127) / 128, 128>>>(src);
    k_buildW<<<(CIN * COUT + 255) / 256, 256>>>(Wz, bz, Wh, bh);

    int propBlocks = (NN + 7) / 8;  // 8 warps (nodes) per 256-thread block
    k_prop<0><<<propBlocks, 256>>>(X, dst);
    k_prop<1><<<propBlocks, 256>>>(X, dst);

    k_gemm<<<(NN + 127) / 128, 512, (CIN * COUT + 128 * 33) * 4>>>(X);
    k_final<<<(NN * FOUT + 255) / 256, 256>>>(out);
}

// round 11
// speedup vs baseline: 1.0460x; 1.0460x over previous
#include <cuda_runtime.h>
#include <math.h>

#define NN 50000
#define EE 800000
#define FIN 32
#define FOUT 64
#define CIN 160    // 5 blocks of 32
#define COUT 128   // 2 gates x 64

typedef unsigned long long ull;

// ---------------- scratch (device globals; no allocation) ----------------
__device__ float g_degin[NN], g_degout[NN];
__device__ float g_rdegin[NN], g_rdegout[NN];
__device__ int   g_cntin[NN], g_cntout[NN], g_fill[NN];
__device__ int   g_instart[NN + 1], g_outstart[NN + 1];
__device__ int   g_bucket[EE];
__device__ int   g_csc_src[EE];
__device__ float g_csc_coef[EE];
__device__ float g_ci[EE];
__device__ int   g_T;   // # edges whose int32 key (dst*N+src) overflows negative
__device__ __align__(16) float g_Y1o[NN * FIN];
__device__ __align__(16) float g_Y1i[NN * FIN];
__device__ __align__(16) float g_U2o[NN * FIN];
__device__ __align__(16) float g_U2i[NN * FIN];
__device__ __align__(16) float g_Wc[CIN * COUT];
__device__ float g_bc[COUT];

// ---------------- f32x2 helpers ----------------
__device__ __forceinline__ void fma2(ull& d, ull a, ull b) {
    asm("fma.rn.f32x2 %0, %1, %2, %3;" : "=l"(d) : "l"(a), "l"(b), "l"(d));
}
__device__ __forceinline__ ull bcast2(float x) {
    ull r; asm("mov.b64 %0, {%1, %1};" : "=l"(r) : "f"(x)); return r;
}
__device__ __forceinline__ float2 unpack2(ull v) {
    float2 f; asm("mov.b64 {%0, %1}, %2;" : "=f"(f.x), "=f"(f.y) : "l"(v)); return f;
}

// ---------------- init: zero counters + build combined weights ----------------
// Combined weight logic (H==0 so only top-32 rows of each 96-row W matter):
//   blk0: W00+W10-W02-W12, blk1: W01, blk2: W11, blk3: 2*W02, blk4: 2*W12
__global__ void k_init(const float* __restrict__ Wz, const float* __restrict__ bz,
                       const float* __restrict__ Wh, const float* __restrict__ bh) {
    int i = blockIdx.x * blockDim.x + threadIdx.x;
    if (i < NN) {
        g_degin[i] = 0.f; g_degout[i] = 0.f;
        g_cntin[i] = 0;   g_cntout[i] = 0;  g_fill[i] = 0;
    }
    if (i == 0) g_T = 0;
    if (i < CIN * COUT) {
        int R = i / COUT, C = i % COUT;
        int gate = C / FOUT, c = C % FOUT;
        const float* W = gate ? Wh : Wz;  // (2,3,96,64)
        int blk = R / 32, r = R % 32;
#define WV(d, k) W[(((d) * 3 + (k)) * 96 + r) * 64 + c]
        float v;
        if (blk == 0)      v = WV(0, 0) + WV(1, 0) - WV(0, 2) - WV(1, 2);
        else if (blk == 1) v = WV(0, 1);
        else if (blk == 2) v = WV(1, 1);
        else if (blk == 3) v = 2.f * WV(0, 2);
        else               v = 2.f * WV(1, 2);
#undef WV
        g_Wc[R * COUT + C] = v;
        if (R == 0) g_bc[C] = gate ? bh[c] : bz[c];
    }
}

// ---------------- histogram (EE divisible by 256 -> full warps) ----------------
__global__ void k_hist(const int* __restrict__ src, const int* __restrict__ dst,
                       const float* __restrict__ w) {
    int j = blockIdx.x * blockDim.x + threadIdx.x;
    int s = src[j], d = dst[j];
    float ww = w[j];
    atomicAdd(&g_cntin[d], 1);
    atomicAdd(&g_degin[d], ww);

    // src is sorted -> equal-src runs are contiguous; warp-segmented reduce
    int lane = threadIdx.x & 31;
    int sprev = __shfl_up_sync(0xffffffffu, s, 1);
    bool leader = (lane == 0) || (s != sprev);
    unsigned bmask = __ballot_sync(0xffffffffu, leader);
    float x = ww;
#pragma unroll
    for (int o = 1; o < 32; o <<= 1) {
        float t = __shfl_down_sync(0xffffffffu, x, o);
        int sd  = __shfl_down_sync(0xffffffffu, s, o);
        if (lane + o < 32 && sd == s) x += t;
    }
    if (leader) {
        unsigned rest = (lane == 31) ? 0u : (bmask & ~((2u << lane) - 1u));
        int next = rest ? (__ffs(rest) - 1) : 32;
        atomicAdd(&g_degout[s], x);
        atomicAdd(&g_cntout[s], next - lane);
    }

    // Reference argsort keys dst*N+src are int32 (JAX x64 off): keys >= 2^31
    // wrap negative and sort FIRST. Count them.
    bool hi = ((long long)d * (long long)NN + (long long)s) >= 2147483648LL;
    unsigned m = __ballot_sync(0xffffffffu, hi);
    if (lane == 0 && m) atomicAdd(&g_T, __popc(m));
}

// ---------------- scans (parallel blocks) + reciprocals ----------------
__device__ void scan_one(const int* cnt, int* out) {
    __shared__ int warpsum[32];
    __shared__ int s_carry;
    if (threadIdx.x == 0) s_carry = 0;
    __syncthreads();
    int lane = threadIdx.x & 31, wid = threadIdx.x >> 5;
    for (int base = 0; base < NN; base += blockDim.x) {
        int i = base + (int)threadIdx.x;
        int v = (i < NN) ? cnt[i] : 0;
        int x = v;
#pragma unroll
        for (int o = 1; o < 32; o <<= 1) {
            int t = __shfl_up_sync(0xffffffff, x, o);
            if (lane >= o) x += t;
        }
        if (lane == 31) warpsum[wid] = x;
        __syncthreads();
        if (wid == 0) {
            int nw = blockDim.x >> 5;
            int ws = (lane < nw) ? warpsum[lane] : 0;
#pragma unroll
            for (int o = 1; o < 32; o <<= 1) {
                int t = __shfl_up_sync(0xffffffff, ws, o);
                if (lane >= o) ws += t;
            }
            warpsum[lane] = ws;
        }
        __syncthreads();
        int incl = x + (wid > 0 ? warpsum[wid - 1] : 0);
        int carry = s_carry;
        if (i < NN) out[i] = carry + incl - v;
        __syncthreads();
        if (threadIdx.x == blockDim.x - 1) s_carry = carry + incl;
        __syncthreads();
    }
    if (threadIdx.x == 0) out[NN] = s_carry;
}

__global__ void k_scan() {
    if (blockIdx.x == 0) {
        scan_one(g_cntin, g_instart);
    } else if (blockIdx.x == 1) {
        scan_one(g_cntout, g_outstart);
    } else {
        for (int i = threadIdx.x; i < NN; i += blockDim.x) {
            g_rdegin[i]  = 1.0f / g_degin[i];   // exact same op as reference
            g_rdegout[i] = 1.0f / g_degout[i];
        }
    }
}

// ---------------- bucket fill (4 edges/thread for MLP) ----------------
__global__ void k_bucket(const int* __restrict__ dst) {
    int base = blockIdx.x * blockDim.x + threadIdx.x;
    int stride = gridDim.x * blockDim.x;
#pragma unroll
    for (int r = 0; r < 4; r++) {
        int j = base + r * stride;
        if (j < EE) {
            int d = dst[j];
            int t = atomicAdd(&g_fill[d], 1);
            g_bucket[g_instart[d] + t] = j;
        }
    }
}

// Per-dst insertion sort (stable by src == by j), then fill CSC arrays.
// Position t is the pure (dst,src) rank; the reference order is a ROTATION:
// the T overflow-key edges come first, so edge at rank t is at reference
// position (t+T) mod E, and its reverse coefficient is 1/deg_in[src[(t+T)%E]].
__global__ void k_sortfill(const int* __restrict__ src) {
    int i = blockIdx.x * blockDim.x + threadIdx.x;
    if (i >= NN) return;
    int T = g_T;
    int b = g_instart[i], e = g_instart[i + 1];
    for (int p = b + 1; p < e; p++) {
        int v = g_bucket[p];
        int q = p - 1;
        while (q >= b && g_bucket[q] > v) { g_bucket[q + 1] = g_bucket[q]; q--; }
        g_bucket[q + 1] = v;
    }
    for (int t = b; t < e; t++) {
        int j = g_bucket[t];
        int s = src[j];
        g_csc_src[t] = s;
        g_csc_coef[t] = g_rdegout[s];
        int tref = t + T; if (tref >= EE) tref -= EE;
        g_ci[j] = g_rdegin[src[tref]];
    }
}

// ---------------- propagation (pure gather, no atomics) ----------------
// PHASE 0: Y1o = P_o X, Y1i = P_i X;  PHASE 1: U2o = P_o Y1o, U2i = P_i Y1i
template <int PHASE>
__global__ void k_prop(const float* __restrict__ X, const int* __restrict__ dst) {
    int warp = (blockIdx.x * blockDim.x + threadIdx.x) >> 5;
    int lane = threadIdx.x & 31;
    if (warp >= NN) return;
    const float* __restrict__ inF = PHASE ? g_Y1o : X;
    const float* __restrict__ inR = PHASE ? g_Y1i : X;
    float* outF = PHASE ? g_U2o : g_Y1o;
    float* outR = PHASE ? g_U2i : g_Y1i;
    int i = warp;

    int b = g_instart[i], e = g_instart[i + 1];
    float a0 = 0.f, a1 = 0.f;
    int t = b;
    for (; t + 1 < e; t += 2) {
        int s0 = g_csc_src[t], s1 = g_csc_src[t + 1];
        float c0 = g_csc_coef[t], c1 = g_csc_coef[t + 1];
        a0 += c0 * inF[s0 * FIN + lane];
        a1 += c1 * inF[s1 * FIN + lane];
    }
    if (t < e) a0 += g_csc_coef[t] * inF[g_csc_src[t] * FIN + lane];

    int b2 = g_outstart[i], e2 = g_outstart[i + 1];
    float r0 = 0.f, r1 = 0.f;
    int j = b2;
    for (; j + 1 < e2; j += 2) {
        int d0 = dst[j], d1 = dst[j + 1];
        float c0 = g_ci[j], c1 = g_ci[j + 1];
        r0 += c0 * inR[d0 * FIN + lane];
        r1 += c1 * inR[d1 * FIN + lane];
    }
    if (j < e2) r0 += g_ci[j] * inR[dst[j] * FIN + lane];

    outF[i * FIN + lane] = a0 + a1;
    outR[i * FIN + lane] = r0 + r1;
}

// ---------------- fused GEMM + epilogue ----------------
// L = [X|Y1o|Y1i|U2o|U2i] @ Wc + bc; out = sigmoid(-z) * tanh(h)
// 512 threads: tx=tid&7 (8 col-groups of 8), ty=tid>>3 (64 node-groups of 2).
// Each thread: 2 nodes x (8 z-cols + 8 h-cols), accumulated as f32x2 pairs.
__global__ __launch_bounds__(512, 2) void k_gemm(const float* __restrict__ X,
                                                 float* __restrict__ out) {
    extern __shared__ float sm[];
    float* Ws = sm;                  // [160][128] = 80KB
    float* Fs = sm + CIN * COUT;     // [128][33] padded = 16.9KB

    int tid = threadIdx.x;
    for (int p = tid; p < CIN * COUT / 4; p += 512)
        ((float4*)Ws)[p] = ((const float4*)g_Wc)[p];

    int nodeBase = blockIdx.x * 128;
    int tx = tid & 7;
    int ty = tid >> 3;

    ull az[2][4], ah[2][4];
#pragma unroll
    for (int a = 0; a < 2; a++)
#pragma unroll
        for (int p = 0; p < 4; p++) { az[a][p] = 0ull; ah[a][p] = 0ull; }

    for (int kc = 0; kc < 5; kc++) {
        __syncthreads();
        const float* A;
        if (kc == 0) A = X;
        else if (kc == 1) A = g_Y1o;
        else if (kc == 2) A = g_Y1i;
        else if (kc == 3) A = g_U2o;
        else A = g_U2i;
        for (int p = tid; p < 128 * 8; p += 512) {
            int nn = p >> 3, kk4 = p & 7;
            int node = nodeBase + nn;
            float4 v = make_float4(0.f, 0.f, 0.f, 0.f);
            if (node < NN) v = ((const float4*)(A + (size_t)node * FIN))[kk4];
            float* dp = &Fs[nn * 33 + kk4 * 4];
            dp[0] = v.x; dp[1] = v.y; dp[2] = v.z; dp[3] = v.w;
        }
        __syncthreads();
#pragma unroll 4
        for (int kk = 0; kk < 32; kk++) {
            int k = kc * 32 + kk;
            ull f0 = bcast2(Fs[(ty * 2) * 33 + kk]);
            ull f1 = bcast2(Fs[(ty * 2 + 1) * 33 + kk]);
            const ulonglong2* wz = (const ulonglong2*)&Ws[k * COUT + tx * 8];
            const ulonglong2* wh = (const ulonglong2*)&Ws[k * COUT + 64 + tx * 8];
            ulonglong2 z01 = wz[0], z23 = wz[1];
            ulonglong2 h01 = wh[0], h23 = wh[1];
            fma2(az[0][0], f0, z01.x); fma2(az[0][1], f0, z01.y);
            fma2(az[0][2], f0, z23.x); fma2(az[0][3], f0, z23.y);
            fma2(ah[0][0], f0, h01.x); fma2(ah[0][1], f0, h01.y);
            fma2(ah[0][2], f0, h23.x); fma2(ah[0][3], f0, h23.y);
            fma2(az[1][0], f1, z01.x); fma2(az[1][1], f1, z01.y);
            fma2(az[1][2], f1, z23.x); fma2(az[1][3], f1, z23.y);
            fma2(ah[1][0], f1, h01.x); fma2(ah[1][1], f1, h01.y);
            fma2(ah[1][2], f1, h23.x); fma2(ah[1][3], f1, h23.y);
        }
    }

    // epilogue: out[node, c] = (1 - sigmoid(z)) * tanh(h)
#pragma unroll
    for (int a = 0; a < 2; a++) {
        int node = nodeBase + ty * 2 + a;
        if (node >= NN) continue;
        float o[8];
#pragma unroll
        for (int p = 0; p < 4; p++) {
            float2 z2 = unpack2(az[a][p]);
            float2 h2 = unpack2(ah[a][p]);
            int c = tx * 8 + p * 2;
#pragma unroll
            for (int q = 0; q < 2; q++) {
                float z = (q ? z2.y : z2.x) + g_bc[c + q];
                float h = (q ? h2.y : h2.x) + g_bc[64 + c + q];
                float sz = __fdividef(1.f, 1.f + __expf(z));   // sigmoid(-z)
                float e2 = __expf(2.f * h);
                float th = 1.f - __fdividef(2.f, e2 + 1.f);    // tanh(h)
                o[p * 2 + q] = sz * th;
            }
        }
        float4* op = (float4*)(out + (size_t)node * FOUT + tx * 8);
        op[0] = make_float4(o[0], o[1], o[2], o[3]);
        op[1] = make_float4(o[4], o[5], o[6], o[7]);
    }
}

// ---------------- launch ----------------
extern "C" void kernel_launch(void* const* d_in, const int* in_sizes, int n_in,
                              void* d_out, int out_size) {
    const float* X  = (const float*)d_in[0];
    const int*   ei = (const int*)d_in[1];
    const float* ew = (const float*)d_in[2];
    const float* Wz = (const float*)d_in[3];
    const float* bz = (const float*)d_in[4];
    // d_in[5]=Wr, d_in[6]=br are mathematically dead (H==0)
    const float* Wh = (const float*)d_in[7];
    const float* bh = (const float*)d_in[8];
    const int* src = ei;
    const int* dst = ei + EE;
    float* out = (float*)d_out;

    (void)in_sizes; (void)n_in; (void)out_size;

    const int gemmSmem = (CIN * COUT + 128 * 33) * 4;
    cudaFuncSetAttribute(k_gemm, cudaFuncAttributeMaxDynamicSharedMemorySize,
                         gemmSmem);

    k_init<<<(NN + 255) / 256, 256>>>(Wz, bz, Wh, bh);
    k_hist<<<EE / 256, 256>>>(src, dst, ew);
    k_scan<<<3, 1024>>>();
    k_bucket<<<(EE / 4 + 255) / 256, 256>>>(dst);
    k_sortfill<<<(NN + 127) / 128, 128>>>(src);

    int propBlocks = (NN + 7) / 8;  // 8 warps (nodes) per 256-thread block
    k_prop<0><<<propBlocks, 256>>>(X, dst);
    k_prop<1><<<propBlocks, 256>>>(X, dst);

    k_gemm<<<(NN + 127) / 128, 512, gemmSmem>>>(X, out);
}

// round 13
// speedup vs baseline: 1.0943x; 1.0461x over previous
#include <cuda_runtime.h>
#include <math.h>

#define NN 50000
#define EE 800000
#define FIN 32
#define FOUT 64
#define CIN 160    // 5 blocks of 32
#define COUT 128   // 2 gates x 64

typedef unsigned long long ull;

// ---------------- scratch (device globals; no allocation) ----------------
__device__ float g_degin[NN], g_degout[NN];
__device__ float g_rdegin[NN], g_rdegout[NN];
__device__ int   g_cntin[NN], g_cntout[NN], g_fill[NN];
__device__ int   g_instart[NN + 1], g_outstart[NN + 1];
__device__ int   g_bucket[EE];
__device__ __align__(16) int2 g_fwd_pack[EE];  // (src, rdegout[src]) in CSC order
__device__ __align__(16) int2 g_rev_pack[EE];  // (dst[j], ci[j]) in edge-id order
__device__ int   g_T;   // # edges whose int32 key (dst*N+src) overflows negative
__device__ __align__(16) float g_Y1o[NN * FIN];
__device__ __align__(16) float g_Y1i[NN * FIN];
__device__ __align__(16) float g_U2o[NN * FIN];
__device__ __align__(16) float g_U2i[NN * FIN];
__device__ __align__(16) float g_Wc[CIN * COUT];
__device__ float g_bc[COUT];

// ---------------- f32x2 helpers ----------------
__device__ __forceinline__ void fma2(ull& d, ull a, ull b) {
    asm("fma.rn.f32x2 %0, %1, %2, %3;" : "=l"(d) : "l"(a), "l"(b), "l"(d));
}
__device__ __forceinline__ ull bcast2(float x) {
    ull r; asm("mov.b64 %0, {%1, %1};" : "=l"(r) : "f"(x)); return r;
}
__device__ __forceinline__ float2 unpack2(ull v) {
    float2 f; asm("mov.b64 {%0, %1}, %2;" : "=f"(f.x), "=f"(f.y) : "l"(v)); return f;
}

// ---------------- init: zero counters + build combined weights ----------------
// H==0 so only top-32 rows of each 96-row W matter:
//   blk0: W00+W10-W02-W12, blk1: W01, blk2: W11, blk3: 2*W02, blk4: 2*W12
__global__ void k_init(const float* __restrict__ Wz, const float* __restrict__ bz,
                       const float* __restrict__ Wh, const float* __restrict__ bh) {
    int i = blockIdx.x * blockDim.x + threadIdx.x;
    if (i < NN) {
        g_degin[i] = 0.f; g_degout[i] = 0.f;
        g_cntin[i] = 0;   g_cntout[i] = 0;  g_fill[i] = 0;
    }
    if (i == 0) g_T = 0;
    if (i < CIN * COUT) {
        int R = i / COUT, C = i % COUT;
        int gate = C / FOUT, c = C % FOUT;
        const float* W = gate ? Wh : Wz;  // (2,3,96,64)
        int blk = R / 32, r = R % 32;
#define WV(d, k) W[(((d) * 3 + (k)) * 96 + r) * 64 + c]
        float v;
        if (blk == 0)      v = WV(0, 0) + WV(1, 0) - WV(0, 2) - WV(1, 2);
        else if (blk == 1) v = WV(0, 1);
        else if (blk == 2) v = WV(1, 1);
        else if (blk == 3) v = 2.f * WV(0, 2);
        else               v = 2.f * WV(1, 2);
#undef WV
        g_Wc[R * COUT + C] = v;
        if (R == 0) g_bc[C] = gate ? bh[c] : bz[c];
    }
}

// ---------------- histogram (EE divisible by 256 -> full warps) ----------------
__global__ void k_hist(const int* __restrict__ src, const int* __restrict__ dst,
                       const float* __restrict__ w) {
    int j = blockIdx.x * blockDim.x + threadIdx.x;
    int s = src[j], d = dst[j];
    float ww = w[j];
    atomicAdd(&g_cntin[d], 1);
    atomicAdd(&g_degin[d], ww);

    // src is sorted -> equal-src runs contiguous; warp-segmented reduce
    int lane = threadIdx.x & 31;
    int sprev = __shfl_up_sync(0xffffffffu, s, 1);
    bool leader = (lane == 0) || (s != sprev);
    unsigned bmask = __ballot_sync(0xffffffffu, leader);
    float x = ww;
#pragma unroll
    for (int o = 1; o < 32; o <<= 1) {
        float t = __shfl_down_sync(0xffffffffu, x, o);
        int sd  = __shfl_down_sync(0xffffffffu, s, o);
        if (lane + o < 32 && sd == s) x += t;
    }
    if (leader) {
        unsigned rest = (lane == 31) ? 0u : (bmask & ~((2u << lane) - 1u));
        int next = rest ? (__ffs(rest) - 1) : 32;
        atomicAdd(&g_degout[s], x);
        atomicAdd(&g_cntout[s], next - lane);
    }

    // Reference argsort keys dst*N+src are int32 (JAX x64 off): keys >= 2^31
    // wrap negative and sort FIRST. Count them.
    bool hi = ((long long)d * (long long)NN + (long long)s) >= 2147483648LL;
    unsigned m = __ballot_sync(0xffffffffu, hi);
    if (lane == 0 && m) atomicAdd(&g_T, __popc(m));
}

// ---------------- scans (parallel blocks) + reciprocals ----------------
__device__ void scan_one(const int* cnt, int* out) {
    __shared__ int warpsum[32];
    __shared__ int s_carry;
    if (threadIdx.x == 0) s_carry = 0;
    __syncthreads();
    int lane = threadIdx.x & 31, wid = threadIdx.x >> 5;
    for (int base = 0; base < NN; base += blockDim.x) {
        int i = base + (int)threadIdx.x;
        int v = (i < NN) ? cnt[i] : 0;
        int x = v;
#pragma unroll
        for (int o = 1; o < 32; o <<= 1) {
            int t = __shfl_up_sync(0xffffffff, x, o);
            if (lane >= o) x += t;
        }
        if (lane == 31) warpsum[wid] = x;
        __syncthreads();
        if (wid == 0) {
            int nw = blockDim.x >> 5;
            int ws = (lane < nw) ? warpsum[lane] : 0;
#pragma unroll
            for (int o = 1; o < 32; o <<= 1) {
                int t = __shfl_up_sync(0xffffffff, ws, o);
                if (lane >= o) ws += t;
            }
            warpsum[lane] = ws;
        }
        __syncthreads();
        int incl = x + (wid > 0 ? warpsum[wid - 1] : 0);
        int carry = s_carry;
        if (i < NN) out[i] = carry + incl - v;
        __syncthreads();
        if (threadIdx.x == blockDim.x - 1) s_carry = carry + incl;
        __syncthreads();
    }
    if (threadIdx.x == 0) out[NN] = s_carry;
}

__global__ void k_scan() {
    if (blockIdx.x == 0) {
        scan_one(g_cntin, g_instart);
    } else if (blockIdx.x == 1) {
        scan_one(g_cntout, g_outstart);
    } else {
        for (int i = threadIdx.x; i < NN; i += blockDim.x) {
            g_rdegin[i]  = 1.0f / g_degin[i];   // exact same op as reference
            g_rdegout[i] = 1.0f / g_degout[i];
        }
    }
}

// ---------------- bucket fill (1 edge/thread: max warps in flight) ----------------
__global__ void k_bucket(const int* __restrict__ dst) {
    int j = blockIdx.x * blockDim.x + threadIdx.x;
    if (j < EE) {
        int d = dst[j];
        int t = atomicAdd(&g_fill[d], 1);
        g_bucket[g_instart[d] + t] = j;
    }
}

// Per-dst insertion sort (stable by src == by j), then fill packed arrays.
// Position t is the pure (dst,src) rank; the reference order is a ROTATION:
// the T overflow-key edges come first, so edge at rank t sits at reference
// position (t+T) mod E, and its reverse coefficient is 1/deg_in[src[(t+T)%E]]
// (norm_in indexed by POSITION in the reference's rev arrays).
__global__ void k_sortfill(const int* __restrict__ src, const int* __restrict__ dst) {
    int i = blockIdx.x * blockDim.x + threadIdx.x;
    if (i >= NN) return;
    int T = g_T;
    int b = g_instart[i], e = g_instart[i + 1];
    for (int p = b + 1; p < e; p++) {
        int v = g_bucket[p];
        int q = p - 1;
        while (q >= b && g_bucket[q] > v) { g_bucket[q + 1] = g_bucket[q]; q--; }
        g_bucket[q + 1] = v;
    }
    for (int t = b; t < e; t++) {
        int j = g_bucket[t];
        int s = src[j];
        g_fwd_pack[t] = make_int2(s, __float_as_int(g_rdegout[s]));
        int tref = t + T; if (tref >= EE) tref -= EE;
        g_rev_pack[j] = make_int2(dst[j], __float_as_int(g_rdegin[src[tref]]));
    }
}

// ---------------- propagation (pure gather, no atomics) ----------------
// PHASE 0: Y1o = P_o X, Y1i = P_i X;  PHASE 1: U2o = P_o Y1o, U2i = P_i Y1i
// Warp = one node; 4 groups of 8 lanes each gather a DIFFERENT neighbor row
// as float4 (8 lanes x 16B = 128B row) -> 4 rows in flight per load instr.
template <int PHASE>
__global__ void k_prop(const float* __restrict__ Xin) {
    int warp = (blockIdx.x * blockDim.x + threadIdx.x) >> 5;
    if (warp >= NN) return;
    int lane = threadIdx.x & 31;
    int g = lane >> 3, sub = lane & 7;
    const float4* __restrict__ inF = (const float4*)(PHASE ? g_Y1o : Xin);
    const float4* __restrict__ inR = (const float4*)(PHASE ? g_Y1i : Xin);
    float4* outF = (float4*)(PHASE ? g_U2o : g_Y1o);
    float4* outR = (float4*)(PHASE ? g_U2i : g_Y1i);
    int i = warp;

    int b  = g_instart[i],  e  = g_instart[i + 1];
    int b2 = g_outstart[i], e2 = g_outstart[i + 1];

    float4 aF = make_float4(0.f, 0.f, 0.f, 0.f);
#pragma unroll 2
    for (int t = b + g; t < e; t += 4) {
        int2 pk = g_fwd_pack[t];
        float c = __int_as_float(pk.y);
        float4 v = inF[pk.x * 8 + sub];
        aF.x += c * v.x; aF.y += c * v.y; aF.z += c * v.z; aF.w += c * v.w;
    }

    float4 aR = make_float4(0.f, 0.f, 0.f, 0.f);
#pragma unroll 2
    for (int j = b2 + g; j < e2; j += 4) {
        int2 pk = g_rev_pack[j];
        float c = __int_as_float(pk.y);
        float4 v = inR[pk.x * 8 + sub];
        aR.x += c * v.x; aR.y += c * v.y; aR.z += c * v.z; aR.w += c * v.w;
    }

    // reduce across the 4 groups (lanes xor 8, 16)
#pragma unroll
    for (int o = 8; o <= 16; o <<= 1) {
        aF.x += __shfl_xor_sync(0xffffffffu, aF.x, o);
        aF.y += __shfl_xor_sync(0xffffffffu, aF.y, o);
        aF.z += __shfl_xor_sync(0xffffffffu, aF.z, o);
        aF.w += __shfl_xor_sync(0xffffffffu, aF.w, o);
        aR.x += __shfl_xor_sync(0xffffffffu, aR.x, o);
        aR.y += __shfl_xor_sync(0xffffffffu, aR.y, o);
        aR.z += __shfl_xor_sync(0xffffffffu, aR.z, o);
        aR.w += __shfl_xor_sync(0xffffffffu, aR.w, o);
    }
    if (g == 0) {
        outF[i * 8 + sub] = aF;
        outR[i * 8 + sub] = aR;
    }
}

// ---------------- fused GEMM + epilogue ----------------
// L = [X|Y1o|Y1i|U2o|U2i] @ Wc + bc; out = sigmoid(-z) * tanh(h)
// 512 threads: tx=tid&7 (8 col-groups of 8), ty=tid>>3 (64 node-groups of 2).
// Each thread: 2 nodes x (8 z-cols + 8 h-cols), accumulated as f32x2 pairs.
__global__ __launch_bounds__(512, 2) void k_gemm(const float* __restrict__ X,
                                                 float* __restrict__ out) {
    extern __shared__ float sm[];
    float* Ws = sm;                  // [160][128] = 80KB
    float* Fs = sm + CIN * COUT;     // [128][33] padded = 16.9KB

    int tid = threadIdx.x;
    for (int p = tid; p < CIN * COUT / 4; p += 512)
        ((float4*)Ws)[p] = ((const float4*)g_Wc)[p];

    int nodeBase = blockIdx.x * 128;
    int tx = tid & 7;
    int ty = tid >> 3;

    ull az[2][4], ah[2][4];
#pragma unroll
    for (int a = 0; a < 2; a++)
#pragma unroll
        for (int p = 0; p < 4; p++) { az[a][p] = 0ull; ah[a][p] = 0ull; }

    for (int kc = 0; kc < 5; kc++) {
        __syncthreads();
        const float* A;
        if (kc == 0) A = X;
        else if (kc == 1) A = g_Y1o;
        else if (kc == 2) A = g_Y1i;
        else if (kc == 3) A = g_U2o;
        else A = g_U2i;
        for (int p = tid; p < 128 * 8; p += 512) {
            int nn = p >> 3, kk4 = p & 7;
            int node = nodeBase + nn;
            float4 v = make_float4(0.f, 0.f, 0.f, 0.f);
            if (node < NN) v = ((const float4*)(A + (size_t)node * FIN))[kk4];
            float* dp = &Fs[nn * 33 + kk4 * 4];
            dp[0] = v.x; dp[1] = v.y; dp[2] = v.z; dp[3] = v.w;
        }
        __syncthreads();
#pragma unroll 4
        for (int kk = 0; kk < 32; kk++) {
            int k = kc * 32 + kk;
            ull f0 = bcast2(Fs[(ty * 2) * 33 + kk]);
            ull f1 = bcast2(Fs[(ty * 2 + 1) * 33 + kk]);
            const ulonglong2* wz = (const ulonglong2*)&Ws[k * COUT + tx * 8];
            const ulonglong2* wh = (const ulonglong2*)&Ws[k * COUT + 64 + tx * 8];
            ulonglong2 z01 = wz[0], z23 = wz[1];
            ulonglong2 h01 = wh[0], h23 = wh[1];
            fma2(az[0][0], f0, z01.x); fma2(az[0][1], f0, z01.y);
            fma2(az[0][2], f0, z23.x); fma2(az[0][3], f0, z23.y);
            fma2(ah[0][0], f0, h01.x); fma2(ah[0][1], f0, h01.y);
            fma2(ah[0][2], f0, h23.x); fma2(ah[0][3], f0, h23.y);
            fma2(az[1][0], f1, z01.x); fma2(az[1][1], f1, z01.y);
            fma2(az[1][2], f1, z23.x); fma2(az[1][3], f1, z23.y);
            fma2(ah[1][0], f1, h01.x); fma2(ah[1][1], f1, h01.y);
            fma2(ah[1][2], f1, h23.x); fma2(ah[1][3], f1, h23.y);
        }
    }

    // epilogue: out[node, c] = (1 - sigmoid(z)) * tanh(h)
#pragma unroll
    for (int a = 0; a < 2; a++) {
        int node = nodeBase + ty * 2 + a;
        if (node >= NN) continue;
        float o[8];
#pragma unroll
        for (int p = 0; p < 4; p++) {
            float2 z2 = unpack2(az[a][p]);
            float2 h2 = unpack2(ah[a][p]);
            int c = tx * 8 + p * 2;
#pragma unroll
            for (int q = 0; q < 2; q++) {
                float z = (q ? z2.y : z2.x) + g_bc[c + q];
                float h = (q ? h2.y : h2.x) + g_bc[64 + c + q];
                float sz = __fdividef(1.f, 1.f + __expf(z));   // sigmoid(-z)
                float e2 = __expf(2.f * h);
                float th = 1.f - __fdividef(2.f, e2 + 1.f);    // tanh(h)
                o[p * 2 + q] = sz * th;
            }
        }
        float4* op = (float4*)(out + (size_t)node * FOUT + tx * 8);
        op[0] = make_float4(o[0], o[1], o[2], o[3]);
        op[1] = make_float4(o[4], o[5], o[6], o[7]);
    }
}

// ---------------- launch ----------------
extern "C" void kernel_launch(void* const* d_in, const int* in_sizes, int n_in,
                              void* d_out, int out_size) {
    const float* X  = (const float*)d_in[0];
    const int*   ei = (const int*)d_in[1];
    const float* ew = (const float*)d_in[2];
    const float* Wz = (const float*)d_in[3];
    const float* bz = (const float*)d_in[4];
    // d_in[5]=Wr, d_in[6]=br are mathematically dead (H==0)
    const float* Wh = (const float*)d_in[7];
    const float* bh = (const float*)d_in[8];
    const int* src = ei;
    const int* dst = ei + EE;
    float* out = (float*)d_out;

    (void)in_sizes; (void)n_in; (void)out_size;

    const int gemmSmem = (CIN * COUT + 128 * 33) * 4;
    cudaFuncSetAttribute(k_gemm, cudaFuncAttributeMaxDynamicSharedMemorySize,
                         gemmSmem);

    k_init<<<(NN + 255) / 256, 256>>>(Wz, bz, Wh, bh);
    k_hist<<<EE / 256, 256>>>(src, dst, ew);
    k_scan<<<3, 1024>>>();
    k_bucket<<<(EE + 255) / 256, 256>>>(dst);
    k_sortfill<<<(NN + 127) / 128, 128>>>(src, dst);

    int propBlocks = (NN + 7) / 8;  // 8 warps (nodes) per 256-thread block
    k_prop<0><<<propBlocks, 256>>>(X);
    k_prop<1><<<propBlocks, 256>>>(X);

    k_gemm<<<(NN + 127) / 128, 512, gemmSmem>>>(X, out);
}